// round 8
// baseline (speedup 1.0000x reference)
#include <cuda_runtime.h>
#include <cuda_bf16.h>
#include <cstdint>
#include <math.h>

typedef uint32_t u32;

#define HDIM 512
#define G4   2048
#define EDIM 256
#define N_SC 640
#define T_SC 128
#define N_CM 640
#define T_CM 64
#define N_ISP 128
#define N_IS_REAL 64
#define T_IS 32

#define KS_HH 32              // 512/16
#define KS_IH 16              // 256/16
#define NB_HH (256*KS_HH*32)  // uint2 elements
#define NB_IH (256*KS_IH*32)

// step kernel smem pipeline
#define KC      64
#define NCH     8             // 512/64
#define ASTR    72            // A tile stride (bf16), conflict-free
#define STG_A   18432         // 2 x 64x72x2B (hi+lo)
#define STG_B   32768         // 2 x 16KB packed fragments (hi+lo)
#define STG     (STG_A + STG_B)        // 51200
#define STEP_SMEM (2*STG)              // 102400

// xproj smem: full-K A tile, 128 rows, 4 chunks of 64 cols, hi+lo
#define XP_CH   (128*ASTR*2)           // bytes per chunk per half = 18432
#define XP_HI   0
#define XP_LO   (4*XP_CH)              // 73728
#define XP_SMEM (8*XP_CH)              // 147456

// ---------------- device globals ----------------
__device__ uint2 g_WhhH[3][NB_HH], g_WhhL[3][NB_HH];
__device__ uint2 g_WihH[3][NB_IH], g_WihL[3][NB_IH];

__device__ __nv_bfloat16 g_ehi_sc[(size_t)N_SC*T_SC*EDIM], g_elo_sc[(size_t)N_SC*T_SC*EDIM];
__device__ __nv_bfloat16 g_ehi_cm[(size_t)N_CM*T_CM*EDIM], g_elo_cm[(size_t)N_CM*T_CM*EDIM];
__device__ __nv_bfloat16 g_ehi_is[(size_t)N_ISP*T_IS*EDIM], g_elo_is[(size_t)N_ISP*T_IS*EDIM];

__device__ float g_xp_sc[(size_t)N_SC*T_SC*G4];
__device__ float g_xp_cm[(size_t)N_CM*T_CM*G4];
__device__ float g_xp_is[(size_t)N_ISP*T_IS*G4];

__device__ __nv_bfloat16 g_hhi_sc[2][N_SC*HDIM], g_hlo_sc[2][N_SC*HDIM];
__device__ __nv_bfloat16 g_hhi_cm[2][N_CM*HDIM], g_hlo_cm[2][N_CM*HDIM];
__device__ __nv_bfloat16 g_hhi_is[2][N_ISP*HDIM], g_hlo_is[2][N_ISP*HDIM];
__device__ float g_c_sc[N_SC*HDIM], g_c_cm[N_CM*HDIM], g_c_is[N_ISP*HDIM];
__device__ float g_hm[N_SC], g_cmm[N_SC];

// ---------------- helpers ----------------
__device__ __forceinline__ void mma_bf16(float* c, const u32* a, const u32* b) {
    asm volatile("mma.sync.aligned.m16n8k16.row.col.f32.bf16.bf16.f32 "
        "{%0,%1,%2,%3}, {%4,%5,%6,%7}, {%8,%9}, {%0,%1,%2,%3};"
        : "+f"(c[0]), "+f"(c[1]), "+f"(c[2]), "+f"(c[3])
        : "r"(a[0]), "r"(a[1]), "r"(a[2]), "r"(a[3]), "r"(b[0]), "r"(b[1]));
}
__device__ __forceinline__ u32 smem_u32(const void* p) {
    u32 a;
    asm("{ .reg .u64 t; cvta.to.shared.u64 t, %1; cvt.u32.u64 %0, t; }" : "=r"(a) : "l"(p));
    return a;
}
__device__ __forceinline__ void cpa16(u32 dst, const void* src) {
    asm volatile("cp.async.cg.shared.global [%0], [%1], 16;" :: "r"(dst), "l"(src));
}
#define CPA_COMMIT() asm volatile("cp.async.commit_group;" ::: "memory")
#define CPA_WAIT0()  asm volatile("cp.async.wait_group 0;" ::: "memory")

__device__ __forceinline__ u32 pk2(float a, float b) {
    __nv_bfloat162 v;
    v.x = __float2bfloat16(a); v.y = __float2bfloat16(b);
    return *(u32*)&v;
}
__device__ __forceinline__ float rsd(float a) {
    return a - __bfloat162float(__float2bfloat16(a));
}
__device__ __forceinline__ float sigf(float x) { return 1.f / (1.f + __expf(-x)); }
__device__ __forceinline__ float tanh_f(float x) { return 2.f / (1.f + __expf(-2.f * x)) - 1.f; }

// ---------------- prep kernels ----------------
__global__ void zero_state_k() {
    int i = blockIdx.x * blockDim.x + threadIdx.x;
    __nv_bfloat16 z = __float2bfloat16(0.f);
    if (i < N_SC * HDIM) {
        g_hhi_sc[0][i] = z; g_hlo_sc[0][i] = z; g_c_sc[i] = 0.f;
        g_hhi_cm[0][i] = z; g_hlo_cm[0][i] = z; g_c_cm[i] = 0.f;
    }
    if (i < N_ISP * HDIM) { g_hhi_is[0][i] = z; g_hlo_is[0][i] = z; g_c_is[i] = 0.f; }
}

__global__ void prep_w(const float* __restrict__ Whh, const float* __restrict__ Wih, int sel) {
    int idx = blockIdx.x * blockDim.x + threadIdx.x;
    if (idx < NB_HH) {
        int lane = idx & 31, rest = idx >> 5;
        int ks = rest % KS_HH, j8 = rest / KS_HH;
        int g = lane >> 2, tq = lane & 3;
        const float* Wr = Whh + (size_t)(j8 * 8 + g) * HDIM + ks * 16 + tq * 2;
        float w0 = Wr[0], w1 = Wr[1], w8 = Wr[8], w9 = Wr[9];
        g_WhhH[sel][idx] = make_uint2(pk2(w0, w1), pk2(w8, w9));
        g_WhhL[sel][idx] = make_uint2(pk2(rsd(w0), rsd(w1)), pk2(rsd(w8), rsd(w9)));
    } else {
        int id2 = idx - NB_HH;
        if (id2 < NB_IH) {
            int lane = id2 & 31, rest = id2 >> 5;
            int ks = rest % KS_IH, j8 = rest / KS_IH;
            int g = lane >> 2, tq = lane & 3;
            const float* Wr = Wih + (size_t)(j8 * 8 + g) * EDIM + ks * 16 + tq * 2;
            float w0 = Wr[0], w1 = Wr[1], w8 = Wr[8], w9 = Wr[9];
            g_WihH[sel][id2] = make_uint2(pk2(w0, w1), pk2(w8, w9));
            g_WihL[sel][id2] = make_uint2(pk2(rsd(w0), rsd(w1)), pk2(rsd(w8), rsd(w9)));
        }
    }
}

__global__ void prep_embed(const int* __restrict__ ids, const float* __restrict__ emb,
                           int sel, int Nreal, int Npad, int T) {
    __nv_bfloat16* hi = sel == 0 ? g_ehi_sc : sel == 1 ? g_ehi_cm : g_ehi_is;
    __nv_bfloat16* lo = sel == 0 ? g_elo_sc : sel == 1 ? g_elo_cm : g_elo_is;
    size_t idx = (size_t)blockIdx.x * blockDim.x + threadIdx.x;
    size_t total = (size_t)Npad * T * 64;
    if (idx >= total) return;
    int q = (int)(idx & 63);
    size_t r = idx >> 6;
    int n = (int)(r % Npad);
    int tt = (int)(r / Npad);
    float4 v = make_float4(0.f, 0.f, 0.f, 0.f);
    if (n < Nreal) {
        int tok = ids[(size_t)n * T + tt];
        v = ((const float4*)(emb + (size_t)tok * EDIM))[q];
    }
    __nv_bfloat16 h0 = __float2bfloat16(v.x), h1 = __float2bfloat16(v.y);
    __nv_bfloat16 h2 = __float2bfloat16(v.z), h3 = __float2bfloat16(v.w);
    size_t o = r * EDIM + (size_t)q * 4;
    __nv_bfloat162* ph = (__nv_bfloat162*)(hi + o);
    __nv_bfloat162* pl = (__nv_bfloat162*)(lo + o);
    ph[0] = __nv_bfloat162(h0, h1); ph[1] = __nv_bfloat162(h2, h3);
    pl[0] = __nv_bfloat162(__float2bfloat16(v.x - __bfloat162float(h0)),
                           __float2bfloat16(v.y - __bfloat162float(h1)));
    pl[1] = __nv_bfloat162(__float2bfloat16(v.z - __bfloat162float(h2)),
                           __float2bfloat16(v.w - __bfloat162float(h3)));
}

// ---------------- xproj: full-K A in smem, loop 16 n-subtiles ----------------
// block = 128 rows; 8 warps = 2 (row halves of 64) x 4 (col quarters of 32)
__global__ void __launch_bounds__(256, 1)
xproj_mma(int sel, const float* __restrict__ bias) {
    extern __shared__ char smem[];
    const __nv_bfloat16* ehi = sel == 0 ? g_ehi_sc : sel == 1 ? g_ehi_cm : g_ehi_is;
    const __nv_bfloat16* elo = sel == 0 ? g_elo_sc : sel == 1 ? g_elo_cm : g_elo_is;
    const uint2* __restrict__ BHp = g_WihH[sel];
    const uint2* __restrict__ BLp = g_WihL[sel];
    float* xp = sel == 0 ? g_xp_sc : sel == 1 ? g_xp_cm : g_xp_is;

    const int tid = threadIdx.x, lane = tid & 31, warp = tid >> 5;
    const int wm = warp & 1, wn = warp >> 1;
    const int g = lane >> 2, tq = lane & 3;
    const int m0 = blockIdx.x * 128;
    const u32 sbase = smem_u32(smem);

    // prologue: load full 128x256 A (hi+lo) via cp.async
#pragma unroll
    for (int q = 0; q < 16; q++) {
        int s = tid + q * 256;            // 4096 segs of 16B
        int r = s >> 5, cq = s & 31;      // row, 8-col segment
        int ck = cq >> 3, q8 = cq & 7;
        u32 dst = (u32)(ck * XP_CH + (r * ASTR + q8 * 8) * 2);
        size_t src = (size_t)(m0 + r) * EDIM + cq * 8;
        cpa16(sbase + XP_HI + dst, ehi + src);
        cpa16(sbase + XP_LO + dst, elo + src);
    }
    CPA_COMMIT();
    CPA_WAIT0();
    __syncthreads();

#pragma unroll 1
    for (int ns = 0; ns < 16; ns++) {
        float acc[4][4][4];
#pragma unroll
        for (int i = 0; i < 4; i++)
#pragma unroll
            for (int j = 0; j < 4; j++)
#pragma unroll
                for (int q = 0; q < 4; q++) acc[i][j][q] = 0.f;

        uint2 BH[2][4], BL[2][4];
        // preload kt=0 B fragments
#pragma unroll
        for (int j = 0; j < 4; j++) {
            int j8 = ns * 16 + wn * 4 + j;
            int bi = (j8 * KS_IH + 0) * 32 + lane;
            BH[0][j] = BHp[bi]; BL[0][j] = BLp[bi];
        }
#pragma unroll
        for (int kt = 0; kt < 16; kt++) {
            int cur = kt & 1, nxt = cur ^ 1;
            if (kt + 1 < 16) {
#pragma unroll
                for (int j = 0; j < 4; j++) {
                    int j8 = ns * 16 + wn * 4 + j;
                    int bi = (j8 * KS_IH + kt + 1) * 32 + lane;
                    BH[nxt][j] = BHp[bi]; BL[nxt][j] = BLp[bi];
                }
            }
            int ck = kt >> 2, kk = kt & 3;
            const __nv_bfloat16* Abh = (const __nv_bfloat16*)(smem + XP_HI + ck * XP_CH);
            const __nv_bfloat16* Abl = (const __nv_bfloat16*)(smem + XP_LO + ck * XP_CH);
            u32 AH[4][4], AL[4][4];
#pragma unroll
            for (int i = 0; i < 4; i++) {
                const __nv_bfloat16* p = Abh + (wm * 64 + i * 16 + g) * ASTR + kk * 16 + tq * 2;
                AH[i][0] = *(const u32*)p;
                AH[i][1] = *(const u32*)(p + 8 * ASTR);
                AH[i][2] = *(const u32*)(p + 8);
                AH[i][3] = *(const u32*)(p + 8 * ASTR + 8);
                const __nv_bfloat16* q2 = Abl + (wm * 64 + i * 16 + g) * ASTR + kk * 16 + tq * 2;
                AL[i][0] = *(const u32*)q2;
                AL[i][1] = *(const u32*)(q2 + 8 * ASTR);
                AL[i][2] = *(const u32*)(q2 + 8);
                AL[i][3] = *(const u32*)(q2 + 8 * ASTR + 8);
            }
#pragma unroll
            for (int j = 0; j < 4; j++) {
                u32 bh[2] = {BH[cur][j].x, BH[cur][j].y};
                u32 bl[2] = {BL[cur][j].x, BL[cur][j].y};
#pragma unroll
                for (int i = 0; i < 4; i++) {
                    mma_bf16(acc[i][j], AH[i], bh);
                    mma_bf16(acc[i][j], AL[i], bh);
                    mma_bf16(acc[i][j], AH[i], bl);
                }
            }
        }
        // write subtile
#pragma unroll
        for (int i = 0; i < 4; i++)
#pragma unroll
            for (int j = 0; j < 4; j++) {
                int row = m0 + wm * 64 + i * 16 + g;
                int col = ns * 128 + wn * 32 + j * 8 + tq * 2;
                *(float2*)&xp[(size_t)row * G4 + col] =
                    make_float2(acc[i][j][0] + bias[col], acc[i][j][1] + bias[col + 1]);
                *(float2*)&xp[(size_t)(row + 8) * G4 + col] =
                    make_float2(acc[i][j][2] + bias[col], acc[i][j][3] + bias[col + 1]);
            }
    }
}

// ---------------- fused recurrent step: cp.async pipelined HMMA + gates -------
// tile: 64 rows x (4 gates x 32 hc). grid: [0,160) sc ; [160,320) cm ; [320,352) is
__global__ void __launch_bounds__(256, 2)
step_mma(int t) {
    extern __shared__ char smem[];
    float* zs = (float*)smem;   // reused after mainloop: [64][132]

    int bid = blockIdx.x;
    const __nv_bfloat16 *hhin, *hlin;
    __nv_bfloat16 *hhout, *hlout;
    const uint2 *__restrict__ BHp, *__restrict__ BLp;
    float* cst; const float* xp;
    int m0, hc0;

    if (bid < 160) {
        BHp = g_WhhH[0]; BLp = g_WhhL[0];
        hhin = g_hhi_sc[t & 1]; hlin = g_hlo_sc[t & 1];
        hhout = g_hhi_sc[(t + 1) & 1]; hlout = g_hlo_sc[(t + 1) & 1];
        cst = g_c_sc; xp = g_xp_sc + (size_t)t * N_SC * G4;
        m0 = (bid >> 4) * 64; hc0 = (bid & 15) * 32;
    } else if (bid < 320) {
        bid -= 160;
        BHp = g_WhhH[1]; BLp = g_WhhL[1];
        hhin = g_hhi_cm[t & 1]; hlin = g_hlo_cm[t & 1];
        hhout = g_hhi_cm[(t + 1) & 1]; hlout = g_hlo_cm[(t + 1) & 1];
        cst = g_c_cm; xp = g_xp_cm + (size_t)t * N_CM * G4;
        m0 = (bid >> 4) * 64; hc0 = (bid & 15) * 32;
    } else {
        bid -= 320;
        BHp = g_WhhH[2]; BLp = g_WhhL[2];
        hhin = g_hhi_is[t & 1]; hlin = g_hlo_is[t & 1];
        hhout = g_hhi_is[(t + 1) & 1]; hlout = g_hlo_is[(t + 1) & 1];
        cst = g_c_is; xp = g_xp_is + (size_t)t * N_ISP * G4;
        m0 = (bid >> 4) * 64; hc0 = (bid & 15) * 32;
    }

    const int tid = threadIdx.x, lane = tid & 31, warp = tid >> 5;
    const int wm = warp & 1, wn = warp >> 1;      // wn = gate
    const int g = lane >> 2, tq = lane & 3;
    const u32 sbase = smem_u32(smem);

    // ---- chunk copy lambda (A 64x64 hi/lo + B 64 frag-groups hi/lo) ----
    auto copy_chunk = [&](int ch, int stg_idx) {
        u32 sa = sbase + stg_idx * STG;
        u32 sbh = sa + STG_A;
        u32 sbl = sbh + 16384;
        // A: 512 segs hi + 512 lo, 2 each per thread
#pragma unroll
        for (int q = 0; q < 2; q++) {
            int s = tid + q * 256;
            int r = s >> 3, q8 = s & 7;
            size_t src = (size_t)(m0 + r) * HDIM + ch * KC + q8 * 8;
            u32 dst = sa + (u32)(r * ASTR + q8 * 8) * 2;
            cpa16(dst, hhin + src);
            cpa16(dst + 9216, hlin + src);
        }
        // B: 1024 segs hi + 1024 lo, 4 each per thread
#pragma unroll
        for (int q = 0; q < 4; q++) {
            int sB = tid * 4 + q;
            int g2 = sB >> 4, s16 = sB & 15;
            int gate = g2 >> 4, jl = (g2 >> 2) & 3, ksl = g2 & 3;
            int j8 = gate * 64 + (hc0 >> 3) + jl;
            int ks = ch * 4 + ksl;
            size_t src = ((size_t)(j8 * KS_HH + ks) * 32 + s16 * 2);
            u32 dst = (u32)(g2 * 256 + s16 * 16);
            cpa16(sbh + dst, BHp + src);
            cpa16(sbl + dst, BLp + src);
        }
        CPA_COMMIT();
    };

    float acc[2][4][4];
#pragma unroll
    for (int i = 0; i < 2; i++)
#pragma unroll
        for (int j = 0; j < 4; j++)
#pragma unroll
            for (int q = 0; q < 4; q++) acc[i][j][q] = 0.f;

    copy_chunk(0, 0);

#pragma unroll 1
    for (int ch = 0; ch < NCH; ch++) {
        CPA_WAIT0();
        __syncthreads();
        if (ch + 1 < NCH) copy_chunk(ch + 1, (ch + 1) & 1);

        const char* stg = smem + (ch & 1) * STG;
        const __nv_bfloat16* Abh = (const __nv_bfloat16*)stg;
        const __nv_bfloat16* Abl = (const __nv_bfloat16*)(stg + 9216);
        const uint2* Bh = (const uint2*)(stg + STG_A);
        const uint2* Bl = (const uint2*)(stg + STG_A + 16384);

#pragma unroll
        for (int ksl = 0; ksl < 4; ksl++) {
            u32 AH[2][4], AL[2][4];
#pragma unroll
            for (int i = 0; i < 2; i++) {
                const __nv_bfloat16* p = Abh + (wm * 32 + i * 16 + g) * ASTR + ksl * 16 + tq * 2;
                AH[i][0] = *(const u32*)p;
                AH[i][1] = *(const u32*)(p + 8 * ASTR);
                AH[i][2] = *(const u32*)(p + 8);
                AH[i][3] = *(const u32*)(p + 8 * ASTR + 8);
                const __nv_bfloat16* q2 = Abl + (wm * 32 + i * 16 + g) * ASTR + ksl * 16 + tq * 2;
                AL[i][0] = *(const u32*)q2;
                AL[i][1] = *(const u32*)(q2 + 8 * ASTR);
                AL[i][2] = *(const u32*)(q2 + 8);
                AL[i][3] = *(const u32*)(q2 + 8 * ASTR + 8);
            }
#pragma unroll
            for (int j = 0; j < 4; j++) {
                int g2 = wn * 16 + j * 4 + ksl;
                uint2 bhv = Bh[g2 * 32 + lane];
                uint2 blv = Bl[g2 * 32 + lane];
                u32 bh[2] = {bhv.x, bhv.y};
                u32 bl[2] = {blv.x, blv.y};
#pragma unroll
                for (int i = 0; i < 2; i++) {
                    mma_bf16(acc[i][j], AH[i], bh);
                    mma_bf16(acc[i][j], AL[i], bh);
                    mma_bf16(acc[i][j], AH[i], bl);
                }
            }
        }
    }

    __syncthreads();
    // stage z into smem: col = gate*32 + hc_local  (gate = wn)
#pragma unroll
    for (int i = 0; i < 2; i++)
#pragma unroll
        for (int j = 0; j < 4; j++) {
            int row = wm * 32 + i * 16 + g;
            int colz = wn * 32 + j * 8 + tq * 2;
            *(float2*)&zs[row * 132 + colz] = make_float2(acc[i][j][0], acc[i][j][1]);
            *(float2*)&zs[(row + 8) * 132 + colz] = make_float2(acc[i][j][2], acc[i][j][3]);
        }
    __syncthreads();

    // pointwise: r = tid>>2, 8 contiguous hidden cols per thread
    {
        int r = tid >> 2;
        int hcq = (tid & 3) * 8;
        int m = m0 + r;
#pragma unroll
        for (int half = 0; half < 2; half++) {
            int hc = hcq + half * 4;
            int hcg = hc0 + hc;
            const float* zr = zs + r * 132 + hc;
            float4 zi = *(const float4*)(zr);
            float4 zf = *(const float4*)(zr + 32);
            float4 zg = *(const float4*)(zr + 64);
            float4 zo = *(const float4*)(zr + 96);
            const float* xr = xp + (size_t)m * G4 + hcg;
            float4 xi = *(const float4*)(xr);
            float4 xf = *(const float4*)(xr + 512);
            float4 xg = *(const float4*)(xr + 1024);
            float4 xo = *(const float4*)(xr + 1536);
            float vi[4] = {zi.x + xi.x, zi.y + xi.y, zi.z + xi.z, zi.w + xi.w};
            float vf[4] = {zf.x + xf.x, zf.y + xf.y, zf.z + xf.z, zf.w + xf.w};
            float vg[4] = {zg.x + xg.x, zg.y + xg.y, zg.z + xg.z, zg.w + xg.w};
            float vo[4] = {zo.x + xo.x, zo.y + xo.y, zo.z + xo.z, zo.w + xo.w};
            float* cp = cst + (size_t)m * HDIM + hcg;
            float4 cv = *(const float4*)cp;
            float cc[4] = {cv.x, cv.y, cv.z, cv.w};
            float hv[4];
#pragma unroll
            for (int q = 0; q < 4; q++) {
                float ig = sigf(vi[q]), fg = sigf(vf[q]);
                float gg = tanh_f(vg[q]), og = sigf(vo[q]);
                float cn = fg * cc[q] + ig * gg;
                cc[q] = cn;
                hv[q] = og * tanh_f(cn);
            }
            *(float4*)cp = make_float4(cc[0], cc[1], cc[2], cc[3]);
            __nv_bfloat16 h0 = __float2bfloat16(hv[0]), h1 = __float2bfloat16(hv[1]);
            __nv_bfloat16 h2 = __float2bfloat16(hv[2]), h3 = __float2bfloat16(hv[3]);
            __nv_bfloat162* ph = (__nv_bfloat162*)(hhout + (size_t)m * HDIM + hcg);
            ph[0] = __nv_bfloat162(h0, h1); ph[1] = __nv_bfloat162(h2, h3);
            __nv_bfloat162* pl = (__nv_bfloat162*)(hlout + (size_t)m * HDIM + hcg);
            pl[0] = __nv_bfloat162(__float2bfloat16(hv[0] - __bfloat162float(h0)),
                                   __float2bfloat16(hv[1] - __bfloat162float(h1)));
            pl[1] = __nv_bfloat162(__float2bfloat16(hv[2] - __bfloat162float(h2)),
                                   __float2bfloat16(hv[3] - __bfloat162float(h3)));
        }
    }
}

// ---------------- merge & final ----------------
__global__ void merge_kernel(const float* __restrict__ Wmh, const float* __restrict__ bmh,
                             const float* __restrict__ Wmc, const float* __restrict__ bmc)
{
    int wg = (blockIdx.x * blockDim.x + threadIdx.x) >> 5;
    int lane = threadIdx.x & 31;
    if (wg >= 2 * N_SC) return;
    int which = (wg >= N_SC);
    int n = which ? wg - N_SC : wg;
    const float* W = which ? Wmc : Wmh;
    float s = 0.f;
    for (int k = lane; k < HDIM; k += 32) {
        size_t i = (size_t)n * HDIM + k;
        float a, b;
        if (which) { a = g_c_sc[i]; b = g_c_cm[i]; }
        else {
            a = __bfloat162float(g_hhi_sc[0][i]) + __bfloat162float(g_hlo_sc[0][i]);
            b = __bfloat162float(g_hhi_cm[0][i]) + __bfloat162float(g_hlo_cm[0][i]);
        }
        s += a * W[k] + b * W[HDIM + k];
    }
#pragma unroll
    for (int off = 16; off > 0; off >>= 1) s += __shfl_down_sync(0xffffffffu, s, off);
    if (lane == 0) {
        if (which) g_cmm[n] = s + bmc[0];
        else       g_hm[n]  = s + bmh[0];
    }
}

__global__ void final_kernel(const float* __restrict__ Wfh, const float* __restrict__ bfh,
                             const float* __restrict__ Wfc, const float* __restrict__ bfc,
                             float* __restrict__ out)
{
    int gw = (blockIdx.x * blockDim.x + threadIdx.x) >> 5;
    int lane = threadIdx.x & 31;
    if (gw >= 2 * 64 * HDIM) return;
    int which = (gw >= 64 * HDIM);
    int rem = which ? gw - 64 * HDIM : gw;
    int b = rem >> 9, j = rem & 511;
    const float* W  = which ? Wfc : Wfh;
    const float* mv = which ? g_cmm : g_hm;
    const int K = 10 + HDIM;
    float s = 0.f;
    for (int k = lane; k < K; k += 32) {
        float x;
        if (k < 10) x = mv[b * 10 + k];
        else {
            size_t i = (size_t)b * HDIM + (k - 10);
            x = which ? g_c_is[i]
                      : __bfloat162float(g_hhi_is[0][i]) + __bfloat162float(g_hlo_is[0][i]);
        }
        s += W[(size_t)j * K + k] * x;
    }
#pragma unroll
    for (int off = 16; off > 0; off >>= 1) s += __shfl_down_sync(0xffffffffu, s, off);
    if (lane == 0) {
        float bias = which ? bfc[j] : bfh[j];
        out[(size_t)which * 64 * HDIM + (size_t)b * HDIM + j] = s + bias;
    }
}

// ---------------- launch ----------------
extern "C" void kernel_launch(void* const* d_in, const int* in_sizes, int n_in,
                              void* d_out, int out_size)
{
    (void)in_sizes; (void)n_in; (void)out_size;
    const int*   comments = (const int*)  d_in[0];
    const int*   cmids    = (const int*)  d_in[1];
    const int*   issue    = (const int*)  d_in[2];
    const float* emb_sc   = (const float*)d_in[3];
    const float* emb_cm   = (const float*)d_in[4];
    const float* emb_is   = (const float*)d_in[5];
    const float* Wih_sc   = (const float*)d_in[6];
    const float* Whh_sc   = (const float*)d_in[7];
    const float* b_sc     = (const float*)d_in[8];
    const float* Wih_cm   = (const float*)d_in[9];
    const float* Whh_cm   = (const float*)d_in[10];
    const float* b_cm     = (const float*)d_in[11];
    const float* Wih_is   = (const float*)d_in[12];
    const float* Whh_is   = (const float*)d_in[13];
    const float* b_is     = (const float*)d_in[14];
    const float* Wmh      = (const float*)d_in[15];
    const float* bmh      = (const float*)d_in[16];
    const float* Wmc      = (const float*)d_in[17];
    const float* bmc      = (const float*)d_in[18];
    const float* Wfh      = (const float*)d_in[19];
    const float* bfh      = (const float*)d_in[20];
    const float* Wfc      = (const float*)d_in[21];
    const float* bfc      = (const float*)d_in[22];

    cudaFuncSetAttribute(xproj_mma, cudaFuncAttributeMaxDynamicSharedMemorySize, XP_SMEM);
    cudaFuncSetAttribute(step_mma, cudaFuncAttributeMaxDynamicSharedMemorySize, STEP_SMEM);

    zero_state_k<<<(N_SC * HDIM + 255) / 256, 256>>>();
    prep_w<<<(NB_HH + NB_IH + 255) / 256, 256>>>(Whh_sc, Wih_sc, 0);
    prep_w<<<(NB_HH + NB_IH + 255) / 256, 256>>>(Whh_cm, Wih_cm, 1);
    prep_w<<<(NB_HH + NB_IH + 255) / 256, 256>>>(Whh_is, Wih_is, 2);
    prep_embed<<<(int)(((size_t)N_SC * T_SC * 64 + 255) / 256), 256>>>(comments, emb_sc, 0, N_SC, N_SC, T_SC);
    prep_embed<<<(int)(((size_t)N_CM * T_CM * 64 + 255) / 256), 256>>>(cmids, emb_cm, 1, N_CM, N_CM, T_CM);
    prep_embed<<<(int)(((size_t)N_ISP * T_IS * 64 + 255) / 256), 256>>>(issue, emb_is, 2, N_IS_REAL, N_ISP, T_IS);

    xproj_mma<<<N_SC * T_SC / 128, 256, XP_SMEM>>>(0, b_sc);
    xproj_mma<<<N_CM * T_CM / 128, 256, XP_SMEM>>>(1, b_cm);
    xproj_mma<<<N_ISP * T_IS / 128, 256, XP_SMEM>>>(2, b_is);

    for (int t = 0; t < T_SC; t++) {
        int blocks = 160 + ((t < T_CM) ? 160 : 0) + ((t < T_IS) ? 32 : 0);
        step_mma<<<blocks, 256, STEP_SMEM>>>(t);
    }

    merge_kernel<<<(2 * N_SC * 32 + 255) / 256, 256>>>(Wmh, bmh, Wmc, bmc);
    final_kernel<<<(2 * 64 * HDIM * 32 + 255) / 256, 256>>>(Wfh, bfh, Wfc, bfc, (float*)d_out);
}